// round 1
// baseline (speedup 1.0000x reference)
#include <cuda_runtime.h>
#include <math.h>

#define NMAX 100000

// ---------------- device scratch (static, allowed) ----------------
__device__ float g_norm2[NMAX];
__device__ float g_hmsg[(size_t)NMAX * 64];

// ---------------- helpers ----------------
__device__ __forceinline__ unsigned tf32r(float x) {
    unsigned r;
    asm("cvt.rna.tf32.f32 %0, %1;" : "=r"(r) : "f"(x));
    return r;
}

__device__ __forceinline__ void mma8(float* c, const unsigned* a, unsigned b0, unsigned b1) {
    asm volatile(
        "mma.sync.aligned.m16n8k8.row.col.f32.tf32.tf32.f32 "
        "{%0,%1,%2,%3}, {%4,%5,%6,%7}, {%8,%9}, {%0,%1,%2,%3};\n"
        : "+f"(c[0]), "+f"(c[1]), "+f"(c[2]), "+f"(c[3])
        : "r"(a[0]), "r"(a[1]), "r"(a[2]), "r"(a[3]), "r"(b0), "r"(b1));
}

__device__ __forceinline__ float fsig(float x) {
    return __fdividef(1.0f, 1.0f + __expf(-x));
}

__device__ __forceinline__ float ftanh(float x) {
    float a = fabsf(x);
    float e = __expf(-2.0f * a);
    float t = __fdividef(1.0f - e, 1.0f + e);
    return copysignf(t, x);
}

// ---------------- kernel 1: per-row squared norms ----------------
__global__ void norm2_kernel(const float* __restrict__ feat, int n) {
    int w = (blockIdx.x * blockDim.x + threadIdx.x) >> 5;
    int lane = threadIdx.x & 31;
    if (w >= n) return;
    float2 v = *(const float2*)(feat + (size_t)w * 64 + lane * 2);
    float s = v.x * v.x + v.y * v.y;
    #pragma unroll
    for (int o = 16; o; o >>= 1) s += __shfl_down_sync(0xffffffffu, s, o);
    if (lane == 0) g_norm2[w] = s;
}

// ---------------- kernel 2: argmax over neighbors + row gather ----------------
__global__ void gather_kernel(const float* __restrict__ feat, const int* __restrict__ src, int n) {
    int w = (blockIdx.x * blockDim.x + threadIdx.x) >> 5;
    int lane = threadIdx.x & 31;
    if (w >= n) return;
    int s = src[(size_t)w * 32 + lane];
    float bv = g_norm2[s];
    int bj = lane;
    #pragma unroll
    for (int o = 16; o; o >>= 1) {
        float ov = __shfl_down_sync(0xffffffffu, bv, o);
        int oj = __shfl_down_sync(0xffffffffu, bj, o);
        if (ov > bv || (ov == bv && oj < bj)) { bv = ov; bj = oj; }
    }
    bj = __shfl_sync(0xffffffffu, bj, 0);          // winning lane (first max)
    int bs = __shfl_sync(0xffffffffu, s, bj);      // its src index
    float2 v = *(const float2*)(feat + (size_t)bs * 64 + lane * 2);
    *(float2*)(g_hmsg + (size_t)w * 64 + lane * 2) = v;
}

// ---------------- kernel 3: fused 3-layer LSTM (tf32 mma) ----------------
// smem layout (floats):
//   Xs   [0, 25088)          : 128 rows x 196 (input, tf32 bits)
//   Ws   [25088, 42496)      : 256 rows x 68  (weight chunk, tf32 bits)  } overlaid
//   Hs   [25088, 34304)      : 128 x 72 (h out)                          } with Ws
//   Cs   [34304, 43520)      : 128 x 72 (c in/out, in-place)             }
//   bsum [43520, 43776)      : 256 combined biases
#define SMEM_FLOATS 43776
#define SMEM_BYTES (SMEM_FLOATS * 4)

__global__ __launch_bounds__(256, 1) void lstm_kernel(
    const float* __restrict__ feature,
    const float* __restrict__ h0, const float* __restrict__ c0,
    const float* __restrict__ wih0, const float* __restrict__ whh0,
    const float* __restrict__ bih0, const float* __restrict__ bhh0,
    const float* __restrict__ wih1, const float* __restrict__ whh1,
    const float* __restrict__ bih1, const float* __restrict__ bhh1,
    const float* __restrict__ wih2, const float* __restrict__ whh2,
    const float* __restrict__ bih2, const float* __restrict__ bhh2,
    float* __restrict__ out, int n)
{
    extern __shared__ float sm[];
    float* Xs = sm;
    float* Ws = sm + 25088;
    float* Hs = sm + 25088;
    float* Cs = sm + 34304;
    float* bsum = sm + 43520;
    unsigned* Xsu = (unsigned*)Xs;
    unsigned* Wsu = (unsigned*)Ws;

    const int tid = threadIdx.x;
    const int lane = tid & 31;
    const int warp = tid >> 5;
    const int wm = warp >> 1, wn = warp & 1;
    const int gid = lane >> 2, tig = lane & 3;
    const int m0w = wm * 32;
    const int m0 = blockIdx.x * 128;

    const float* wihA[3] = {wih0, wih1, wih2};
    const float* whhA[3] = {whh0, whh1, whh2};
    const float* bihA[3] = {bih0, bih1, bih2};
    const float* bhhA[3] = {bhh0, bhh1, bhh2};
    const size_t nd = (size_t)n * 64;
    float* out_hs = out + nd;
    float* out_cs = out + 4 * nd;

    // ---- build Xs for layer 0: [hmsg | feature | h0[0]] ----
    #pragma unroll 4
    for (int i = 0; i < 32; i++) {
        int idx = tid + (i << 8);
        int m = idx >> 6, d = idx & 63;
        int node = m0 + m;
        float a = 0.f, b = 0.f, c = 0.f;
        if (node < n) {
            size_t off = (size_t)node * 64 + d;
            a = g_hmsg[off];
            b = feature[off];
            c = h0[off];
        }
        int base = m * 196;
        Xsu[base + d] = tf32r(a);
        Xsu[base + 64 + d] = tf32r(b);
        Xsu[base + 128 + d] = tf32r(c);
    }

    for (int l = 0; l < 3; l++) {
        bsum[tid] = bihA[l][tid] + bhhA[l][tid];
        __syncthreads();

        float acc[2][16][4];
        #pragma unroll
        for (int mf = 0; mf < 2; mf++)
            #pragma unroll
            for (int f = 0; f < 16; f++)
                #pragma unroll
                for (int p = 0; p < 4; p++) acc[mf][f][p] = 0.f;

        const int nch = (l == 0) ? 3 : 2;
        for (int ch = 0; ch < nch; ch++) {
            const float* wp;
            int ks, ko;
            if (l == 0) {
                if (ch < 2) { wp = wihA[0]; ks = 128; ko = ch * 64; }
                else        { wp = whhA[0]; ks = 64;  ko = 0; }
            } else {
                wp = (ch == 0) ? wihA[l] : whhA[l];
                ks = 64; ko = 0;
            }
            // stage weight chunk: Ws[n][kk] = W[n][ko+kk] (coalesced reads)
            #pragma unroll 4
            for (int i = 0; i < 64; i++) {
                int idx = tid + (i << 8);
                int nn = idx >> 6, kk = idx & 63;
                Wsu[nn * 68 + kk] = tf32r(wp[(size_t)nn * ks + ko + kk]);
            }
            __syncthreads();

            const int kbase = ch << 6;
            #pragma unroll
            for (int k8 = 0; k8 < 8; k8++) {
                unsigned a[2][4];
                int kc = kbase + k8 * 8 + tig;
                #pragma unroll
                for (int mf = 0; mf < 2; mf++) {
                    int r = m0w + mf * 16 + gid;
                    a[mf][0] = Xsu[r * 196 + kc];
                    a[mf][1] = Xsu[(r + 8) * 196 + kc];
                    a[mf][2] = Xsu[r * 196 + kc + 4];
                    a[mf][3] = Xsu[(r + 8) * 196 + kc + 4];
                }
                int krow = k8 * 8 + tig;
                #pragma unroll
                for (int f = 0; f < 16; f++) {
                    int nc = (f >> 2) * 64 + wn * 32 + (f & 3) * 8 + gid;
                    unsigned b0 = Wsu[nc * 68 + krow];
                    unsigned b1 = Wsu[nc * 68 + krow + 4];
                    mma8(acc[0][f], a[0], b0, b1);
                    mma8(acc[1][f], a[1], b0, b1);
                }
            }
            __syncthreads();
        }

        // ---- stage c_prev (coalesced) ----
        const float* cg = c0 + (size_t)l * nd;
        #pragma unroll
        for (int i = 0; i < 8; i++) {
            int f4 = tid + (i << 8);
            int m = f4 >> 4, dq = (f4 & 15) << 2;
            int node = m0 + m;
            float4 v = make_float4(0.f, 0.f, 0.f, 0.f);
            if (node < n) v = *(const float4*)(cg + (size_t)node * 64 + dq);
            *(float4*)&Cs[m * 72 + dq] = v;
        }
        __syncthreads();

        // ---- elementwise LSTM cell (all 4 gates per thread, in regs) ----
        #pragma unroll
        for (int mf = 0; mf < 2; mf++)
            #pragma unroll
            for (int j = 0; j < 4; j++)
                #pragma unroll
                for (int p = 0; p < 4; p++) {
                    int m = m0w + mf * 16 + gid + ((p & 2) ? 8 : 0);
                    int d = wn * 32 + j * 8 + 2 * tig + (p & 1);
                    float iv = acc[mf][j][p]      + bsum[d];
                    float fv = acc[mf][4 + j][p]  + bsum[64 + d];
                    float gv = acc[mf][8 + j][p]  + bsum[128 + d];
                    float ov = acc[mf][12 + j][p] + bsum[192 + d];
                    float cp = Cs[m * 72 + d];
                    float cn = fsig(fv) * cp + fsig(iv) * ftanh(gv);
                    float hn = fsig(ov) * ftanh(cn);
                    Cs[m * 72 + d] = cn;
                    Hs[m * 72 + d] = hn;
                }
        __syncthreads();

        // ---- coalesced writeback + build next layer's Xs ----
        const float* h0n = h0 + (size_t)(l + 1) * nd;
        #pragma unroll
        for (int i = 0; i < 8; i++) {
            int f4 = tid + (i << 8);
            int m = f4 >> 4, dq = (f4 & 15) << 2;
            int node = m0 + m;
            float4 h4 = *(float4*)&Hs[m * 72 + dq];
            float4 c4 = *(float4*)&Cs[m * 72 + dq];
            if (node < n) {
                size_t o = (size_t)l * nd + (size_t)node * 64 + dq;
                *(float4*)(out_hs + o) = h4;
                *(float4*)(out_cs + o) = c4;
                if (l == 2) *(float4*)(out + (size_t)node * 64 + dq) = h4;
            }
            if (l < 2) {
                int base = m * 196 + dq;
                if (node < n) {
                    Xsu[base]      = tf32r(h4.x);
                    Xsu[base + 1]  = tf32r(h4.y);
                    Xsu[base + 2]  = tf32r(h4.z);
                    Xsu[base + 3]  = tf32r(h4.w);
                    float4 hh = *(const float4*)(h0n + (size_t)node * 64 + dq);
                    Xsu[base + 64] = tf32r(hh.x);
                    Xsu[base + 65] = tf32r(hh.y);
                    Xsu[base + 66] = tf32r(hh.z);
                    Xsu[base + 67] = tf32r(hh.w);
                } else {
                    Xsu[base] = 0u; Xsu[base + 1] = 0u; Xsu[base + 2] = 0u; Xsu[base + 3] = 0u;
                    Xsu[base + 64] = 0u; Xsu[base + 65] = 0u; Xsu[base + 66] = 0u; Xsu[base + 67] = 0u;
                }
            }
        }
        __syncthreads();
    }
}

// ---------------- launch ----------------
extern "C" void kernel_launch(void* const* d_in, const int* in_sizes, int n_in,
                              void* d_out, int out_size) {
    const float* feature = (const float*)d_in[0];
    const int* src       = (const int*)d_in[1];
    const float* h0      = (const float*)d_in[2];
    const float* c0      = (const float*)d_in[3];
    const float* wih0    = (const float*)d_in[4];
    const float* whh0    = (const float*)d_in[5];
    const float* bih0    = (const float*)d_in[6];
    const float* bhh0    = (const float*)d_in[7];
    const float* wih1    = (const float*)d_in[8];
    const float* whh1    = (const float*)d_in[9];
    const float* bih1    = (const float*)d_in[10];
    const float* bhh1    = (const float*)d_in[11];
    const float* wih2    = (const float*)d_in[12];
    const float* whh2    = (const float*)d_in[13];
    const float* bih2    = (const float*)d_in[14];
    const float* bhh2    = (const float*)d_in[15];
    float* out = (float*)d_out;

    int n = in_sizes[0] / 64;

    cudaFuncSetAttribute(lstm_kernel, cudaFuncAttributeMaxDynamicSharedMemorySize, SMEM_BYTES);

    int wblocks = (n + 7) / 8;  // 8 warps (nodes) per 256-thread block
    norm2_kernel<<<wblocks, 256>>>(feature, n);
    gather_kernel<<<wblocks, 256>>>(feature, src, n);

    int lblocks = (n + 127) / 128;
    lstm_kernel<<<lblocks, 256, SMEM_BYTES>>>(
        feature, h0, c0,
        wih0, whh0, bih0, bhh0,
        wih1, whh1, bih1, bhh1,
        wih2, whh2, bih2, bhh2,
        out, n);
}

// round 4
// speedup vs baseline: 2.0735x; 2.0735x over previous
#include <cuda_runtime.h>
#include <cstdint>
#include <math.h>

#define NMAX 100000

// ---------------- device scratch ----------------
__device__ float g_norm2[NMAX];
__device__ float g_hmsg[(size_t)NMAX * 64];

// ---------------- helpers ----------------
__device__ __forceinline__ unsigned tf32r(float x) {
    unsigned r;
    asm("cvt.rna.tf32.f32 %0, %1;" : "=r"(r) : "f"(x));
    return r;
}
__device__ __forceinline__ void mma8(float* c, const unsigned* a, unsigned b0, unsigned b1) {
    asm volatile(
        "mma.sync.aligned.m16n8k8.row.col.f32.tf32.tf32.f32 "
        "{%0,%1,%2,%3}, {%4,%5,%6,%7}, {%8,%9}, {%0,%1,%2,%3};\n"
        : "+f"(c[0]), "+f"(c[1]), "+f"(c[2]), "+f"(c[3])
        : "r"(a[0]), "r"(a[1]), "r"(a[2]), "r"(a[3]), "r"(b0), "r"(b1));
}
__device__ __forceinline__ float fsig(float x) {
    return __fdividef(1.0f, 1.0f + __expf(-x));
}
__device__ __forceinline__ float ftanh(float x) {
    float a = fabsf(x);
    float e = __expf(-2.0f * a);
    float t = __fdividef(1.0f - e, 1.0f + e);
    return copysignf(t, x);
}
__device__ __forceinline__ uint32_t smem_u32(const void* p) {
    uint32_t a;
    asm("{ .reg .u64 t; cvta.to.shared.u64 t, %1; cvt.u32.u64 %0, t; }" : "=r"(a) : "l"(p));
    return a;
}
__device__ __forceinline__ void cp16(uint32_t dst, const float* src) {
    asm volatile("cp.async.ca.shared.global [%0], [%1], 16;" :: "r"(dst), "l"(src) : "memory");
}
__device__ __forceinline__ void cp_commit() {
    asm volatile("cp.async.commit_group;" ::: "memory");
}
__device__ __forceinline__ void cp_wait1() {
    asm volatile("cp.async.wait_group 1;" ::: "memory");
}
__device__ __forceinline__ void cp_wait0() {
    asm volatile("cp.async.wait_group 0;" ::: "memory");
}

// ---------------- SMEM layout (bytes) ----------------
// A: 128 rows x 196 cols (tf32 bits), stride 196 -> 100352 B
// B: 2 buffers x (128 rows x 36 cols fp32) -> 2 x 18432 B
// bsum: 256 floats
#define A_OFF     0
#define B_OFF     100352
#define BBUF_SZ   18432
#define BSUM_OFF  (B_OFF + 2 * BBUF_SZ)
#define SMEM_BYTES (BSUM_OFF + 1024)

// ---------------- kernel 1: per-row squared norms ----------------
__global__ void norm2_kernel(const float* __restrict__ feat, int n) {
    int w = (blockIdx.x * blockDim.x + threadIdx.x) >> 5;
    int lane = threadIdx.x & 31;
    if (w >= n) return;
    float2 v = *(const float2*)(feat + (size_t)w * 64 + lane * 2);
    float s = v.x * v.x + v.y * v.y;
    #pragma unroll
    for (int o = 16; o; o >>= 1) s += __shfl_down_sync(0xffffffffu, s, o);
    if (lane == 0) g_norm2[w] = s;
}

// ---------------- kernel 2: argmax over neighbors + row gather ----------------
__global__ void gather_kernel(const float* __restrict__ feat, const int* __restrict__ src, int n) {
    int w = (blockIdx.x * blockDim.x + threadIdx.x) >> 5;
    int lane = threadIdx.x & 31;
    if (w >= n) return;
    int s = src[(size_t)w * 32 + lane];
    float bv = g_norm2[s];
    int bj = lane;
    #pragma unroll
    for (int o = 16; o; o >>= 1) {
        float ov = __shfl_down_sync(0xffffffffu, bv, o);
        int oj = __shfl_down_sync(0xffffffffu, bj, o);
        if (ov > bv || (ov == bv && oj < bj)) { bv = ov; bj = oj; }
    }
    bj = __shfl_sync(0xffffffffu, bj, 0);
    int bs = __shfl_sync(0xffffffffu, s, bj);
    float2 v = *(const float2*)(feat + (size_t)bs * 64 + lane * 2);
    *(float2*)(g_hmsg + (size_t)w * 64 + lane * 2) = v;
}

// ---------------- kernel 3: fused 3-layer LSTM (tf32 mma.sync, N-split) ----------------
__global__ __launch_bounds__(256) void lstm_kernel(
    const float* __restrict__ feature,
    const float* __restrict__ h0, const float* __restrict__ c0,
    const float* __restrict__ wih0, const float* __restrict__ whh0,
    const float* __restrict__ bih0, const float* __restrict__ bhh0,
    const float* __restrict__ wih1, const float* __restrict__ whh1,
    const float* __restrict__ bih1, const float* __restrict__ bhh1,
    const float* __restrict__ wih2, const float* __restrict__ whh2,
    const float* __restrict__ bih2, const float* __restrict__ bhh2,
    float* __restrict__ out, int n)
{
    extern __shared__ char smem[];
    unsigned* Xsu = (unsigned*)(smem + A_OFF);
    float* bsum = (float*)(smem + BSUM_OFF);
    const uint32_t sbase = smem_u32(smem);

    const int tid = threadIdx.x;
    const int lane = tid & 31;
    const int warp = tid >> 5;
    const int wm = warp >> 1, wn = warp & 1;
    const int gid = lane >> 2, tig = lane & 3;
    const int m0w = wm * 32;
    const int m0 = blockIdx.x * 128;

    // cp.async staging role: each thread copies 64B of one row
    const int rp = tid >> 1;        // pass-local row 0..127
    const int part = tid & 1;       // which 64B half of the 32-float row
    const int gP0 = (rp >> 5) * 64 + (rp & 31);        // global W row, pass 0
    const uint32_t bdst_local = (uint32_t)(rp * 144 + part * 64);

    const float* wihA[3] = {wih0, wih1, wih2};
    const float* whhA[3] = {whh0, whh1, whh2};
    const float* bihA[3] = {bih0, bih1, bih2};
    const float* bhhA[3] = {bhh0, bhh1, bhh2};
    const size_t nd = (size_t)n * 64;
    float* out_hs = out + nd;
    float* out_cs = out + 4 * nd;

    // ---- hoisted prologue: stage (l=0,p=0) chunks 0,1 (wih0 k[0,32),[32,64)) ----
    {
        const float* s0 = wih0 + (size_t)gP0 * 128 + part * 16;
        uint32_t d0 = sbase + B_OFF + bdst_local;
        #pragma unroll
        for (int q = 0; q < 4; q++) cp16(d0 + q * 16, s0 + q * 4);
        cp_commit();
        const float* s1 = s0 + 32;
        uint32_t d1 = sbase + B_OFF + BBUF_SZ + bdst_local;
        #pragma unroll
        for (int q = 0; q < 4; q++) cp16(d1 + q * 16, s1 + q * 4);
        cp_commit();
    }

    // ---- stage A for layer 0: [hmsg | feature | h0[0]], K=192, rna tf32 ----
    #pragma unroll 4
    for (int i = 0; i < 24; i++) {
        int idx = tid + (i << 8);
        int m = idx / 48, k4 = idx - m * 48;
        int node = m0 + m;
        float4 v = make_float4(0.f, 0.f, 0.f, 0.f);
        if (node < n) {
            size_t off = (size_t)node * 64;
            if (k4 < 16)      v = *(const float4*)(g_hmsg + off + k4 * 4);
            else if (k4 < 32) v = *(const float4*)(feature + off + (k4 - 16) * 4);
            else              v = *(const float4*)(h0 + off + (k4 - 32) * 4);
        }
        uint4 t;
        t.x = tf32r(v.x); t.y = tf32r(v.y); t.z = tf32r(v.z); t.w = tf32r(v.w);
        *(uint4*)(&Xsu[m * 196 + k4 * 4]) = t;
    }

    for (int l = 0; l < 3; l++) {
        bsum[tid] = bihA[l][tid] + bhhA[l][tid];
        const int ncg = (l == 0) ? 6 : 4;

        for (int p = 0; p < 2; p++) {
            const int grow = gP0 + p * 32;

            // prologue staging (skip for l=0,p=0: hoisted above)
            if (!(l == 0 && p == 0)) {
                #pragma unroll 1
                for (int c = 0; c < 2; c++) {
                    const float* wp; int rs, ko;
                    if (l == 0) {
                        if (c < 4) { wp = wih0; rs = 128; ko = c * 32; }
                        else       { wp = whh0; rs = 64;  ko = (c - 4) * 32; }
                    } else {
                        if (c < 2) { wp = wihA[l]; rs = 64; ko = c * 32; }
                        else       { wp = whhA[l]; rs = 64; ko = (c - 2) * 32; }
                    }
                    const float* src = wp + (size_t)grow * rs + ko + part * 16;
                    uint32_t dst = sbase + B_OFF + (c & 1) * BBUF_SZ + bdst_local;
                    #pragma unroll
                    for (int q = 0; q < 4; q++) cp16(dst + q * 16, src + q * 4);
                    cp_commit();
                }
            }

            float acc[2][8][4];
            #pragma unroll
            for (int mf = 0; mf < 2; mf++)
                #pragma unroll
                for (int f = 0; f < 8; f++)
                    #pragma unroll
                    for (int q = 0; q < 4; q++) acc[mf][f][q] = 0.f;

            #pragma unroll 1
            for (int c = 0; c < ncg; c++) {
                if (c < ncg - 1) cp_wait1(); else cp_wait0();
                __syncthreads();

                const unsigned* Bs = (const unsigned*)(smem + B_OFF + (c & 1) * BBUF_SZ);
                const int kbase = c * 32;
                #pragma unroll
                for (int k8 = 0; k8 < 4; k8++) {
                    const int kc = kbase + k8 * 8 + tig;
                    unsigned a[2][4];
                    #pragma unroll
                    for (int mf = 0; mf < 2; mf++) {
                        int r = m0w + mf * 16 + gid;
                        a[mf][0] = Xsu[r * 196 + kc];
                        a[mf][1] = Xsu[(r + 8) * 196 + kc];
                        a[mf][2] = Xsu[r * 196 + kc + 4];
                        a[mf][3] = Xsu[(r + 8) * 196 + kc + 4];
                    }
                    const int krow = k8 * 8 + tig;
                    #pragma unroll
                    for (int f = 0; f < 8; f++) {
                        int nc = (f >> 1) * 32 + wn * 16 + (f & 1) * 8 + gid;
                        unsigned b0 = Bs[nc * 36 + krow];
                        unsigned b1 = Bs[nc * 36 + krow + 4];
                        mma8(acc[0][f], a[0], b0, b1);
                        mma8(acc[1][f], a[1], b0, b1);
                    }
                }
                __syncthreads();

                // re-stage chunk c+2 into buffer (c+2)&1
                int c2 = c + 2;
                if (c2 < ncg) {
                    const float* wp; int rs, ko;
                    if (l == 0) {
                        if (c2 < 4) { wp = wih0; rs = 128; ko = c2 * 32; }
                        else        { wp = whh0; rs = 64;  ko = (c2 - 4) * 32; }
                    } else {
                        if (c2 < 2) { wp = wihA[l]; rs = 64; ko = c2 * 32; }
                        else        { wp = whhA[l]; rs = 64; ko = (c2 - 2) * 32; }
                    }
                    const float* src = wp + (size_t)grow * rs + ko + part * 16;
                    uint32_t dst = sbase + B_OFF + (c2 & 1) * BBUF_SZ + bdst_local;
                    #pragma unroll
                    for (int q = 0; q < 4; q++) cp16(dst + q * 16, src + q * 4);
                    cp_commit();
                }
            }

            // ---------------- epilogue for this pass ----------------
            {
                const float* cg = c0 + (size_t)l * nd;
                const float* h0n = h0 + (size_t)(l + 1) * nd;  // used only when l < 2
                float* hs_l = out_hs + (size_t)l * nd;
                float* cs_l = out_cs + (size_t)l * nd;

                #pragma unroll
                for (int mf = 0; mf < 2; mf++)
                    #pragma unroll
                    for (int jf = 0; jf < 2; jf++) {
                        const int d0 = p * 32 + wn * 16 + jf * 8 + 2 * tig;
                        #pragma unroll
                        for (int rh = 0; rh < 2; rh++) {
                            const int row = m0w + mf * 16 + gid + rh * 8;
                            const int node = m0 + row;
                            const bool valid = node < n;
                            const size_t noff = (size_t)node * 64;
                            float2 cp2 = make_float2(0.f, 0.f);
                            if (valid) cp2 = *(const float2*)(cg + noff + d0);
                            float hv[2], cv[2];
                            #pragma unroll
                            for (int q = 0; q < 2; q++) {
                                const int pp = rh * 2 + q;
                                const int d = d0 + q;
                                float iv = acc[mf][0 + jf][pp] + bsum[d];
                                float fv = acc[mf][2 + jf][pp] + bsum[64 + d];
                                float gv = acc[mf][4 + jf][pp] + bsum[128 + d];
                                float ov = acc[mf][6 + jf][pp] + bsum[192 + d];
                                float cprev = q ? cp2.y : cp2.x;
                                float cn = fsig(fv) * cprev + fsig(iv) * ftanh(gv);
                                hv[q] = fsig(ov) * ftanh(cn);
                                cv[q] = cn;
                            }
                            if (valid) {
                                *(float2*)(hs_l + noff + d0) = make_float2(hv[0], hv[1]);
                                *(float2*)(cs_l + noff + d0) = make_float2(cv[0], cv[1]);
                                if (l == 2) *(float2*)(out + noff + d0) = make_float2(hv[0], hv[1]);
                            }
                            // A-tile rebuild ONLY after the layer's final MMA pass (p==1);
                            // doing it at p==0 corrupts the A tile pass 1 still reads.
                            if (l < 2 && p == 1) {
                                // own h -> A[k=d0], h0[l+1] -> A[k=64+d0]
                                Xsu[row * 196 + d0]     = tf32r(hv[0]);
                                Xsu[row * 196 + d0 + 1] = tf32r(hv[1]);
                                float2 hh = make_float2(0.f, 0.f);
                                if (valid) hh = *(const float2*)(h0n + noff + d0);
                                Xsu[row * 196 + 64 + d0]     = tf32r(hh.x);
                                Xsu[row * 196 + 64 + d0 + 1] = tf32r(hh.y);
                                // pass-0 columns: reload h from global (CTA-coherent after syncs)
                                const int dp = d0 - 32;
                                float2 hp = make_float2(0.f, 0.f), h2 = make_float2(0.f, 0.f);
                                if (valid) {
                                    hp = *(const float2*)(hs_l + noff + dp);
                                    h2 = *(const float2*)(h0n + noff + dp);
                                }
                                Xsu[row * 196 + dp]          = tf32r(hp.x);
                                Xsu[row * 196 + dp + 1]      = tf32r(hp.y);
                                Xsu[row * 196 + 64 + dp]     = tf32r(h2.x);
                                Xsu[row * 196 + 64 + dp + 1] = tf32r(h2.y);
                            }
                        }
                    }
                __syncthreads();
            }
        }
    }
}

// ---------------- launch ----------------
extern "C" void kernel_launch(void* const* d_in, const int* in_sizes, int n_in,
                              void* d_out, int out_size) {
    const float* feature = (const float*)d_in[0];
    const int* src       = (const int*)d_in[1];
    const float* h0      = (const float*)d_in[2];
    const float* c0      = (const float*)d_in[3];
    const float* wih0    = (const float*)d_in[4];
    const float* whh0    = (const float*)d_in[5];
    const float* bih0    = (const float*)d_in[6];
    const float* bhh0    = (const float*)d_in[7];
    const float* wih1    = (const float*)d_in[8];
    const float* whh1    = (const float*)d_in[9];
    const float* bih1    = (const float*)d_in[10];
    const float* bhh1    = (const float*)d_in[11];
    const float* wih2    = (const float*)d_in[12];
    const float* whh2    = (const float*)d_in[13];
    const float* bih2    = (const float*)d_in[14];
    const float* bhh2    = (const float*)d_in[15];
    float* out = (float*)d_out;

    int n = in_sizes[0] / 64;

    cudaFuncSetAttribute(lstm_kernel, cudaFuncAttributeMaxDynamicSharedMemorySize, SMEM_BYTES);

    int wblocks = (n + 7) / 8;
    norm2_kernel<<<wblocks, 256>>>(feature, n);
    gather_kernel<<<wblocks, 256>>>(feature, src, n);

    int lblocks = (n + 127) / 128;
    lstm_kernel<<<lblocks, 256, SMEM_BYTES>>>(
        feature, h0, c0,
        wih0, whh0, bih0, bhh0,
        wih1, whh1, bih1, bhh1,
        wih2, whh2, bih2, bhh2,
        out, n);
}

// round 6
// speedup vs baseline: 3.9293x; 1.8950x over previous
#include <cuda_runtime.h>
#include <cuda_fp16.h>
#include <cstdint>
#include <math.h>

#define NMAX 100000

// ---------------- device scratch ----------------
__device__ float g_norm2[NMAX];
__device__ float g_hmsg[(size_t)NMAX * 64];
// fp16 weights: wih0[256x128] | whh0[256x64] | wih1 | whh1 | wih2 | whh2 (each 256x64)
__device__ __align__(16) __half g_w16[114688];

// ---------------- helpers ----------------
__device__ __forceinline__ void mma16(float* c, const unsigned* a, unsigned b0, unsigned b1) {
    asm volatile(
        "mma.sync.aligned.m16n8k16.row.col.f32.f16.f16.f32 "
        "{%0,%1,%2,%3}, {%4,%5,%6,%7}, {%8,%9}, {%0,%1,%2,%3};\n"
        : "+f"(c[0]), "+f"(c[1]), "+f"(c[2]), "+f"(c[3])
        : "r"(a[0]), "r"(a[1]), "r"(a[2]), "r"(a[3]), "r"(b0), "r"(b1));
}
__device__ __forceinline__ float tanha(float x) {
    float y;
    asm("tanh.approx.f32 %0, %1;" : "=f"(y) : "f"(x));
    return y;
}
__device__ __forceinline__ float fsig(float x) {          // sigmoid via 1-MUFU tanh
    return fmaf(0.5f, tanha(0.5f * x), 0.5f);
}
__device__ __forceinline__ float ftanh(float x) {         // accurate tanh (exp-based)
    float a = fabsf(x);
    float e = __expf(-2.0f * a);
    float t = __fdividef(1.0f - e, 1.0f + e);
    return copysignf(t, x);
}
__device__ __forceinline__ uint32_t smem_u32(const void* p) {
    uint32_t a;
    asm("{ .reg .u64 t; cvta.to.shared.u64 t, %1; cvt.u32.u64 %0, t; }" : "=r"(a) : "l"(p));
    return a;
}
__device__ __forceinline__ void cp16(uint32_t dst, const void* src) {
    asm volatile("cp.async.ca.shared.global [%0], [%1], 16;" :: "r"(dst), "l"(src) : "memory");
}
__device__ __forceinline__ void cp_commit() { asm volatile("cp.async.commit_group;" ::: "memory"); }
__device__ __forceinline__ void cp_wait1()  { asm volatile("cp.async.wait_group 1;" ::: "memory"); }
__device__ __forceinline__ void cp_wait0()  { asm volatile("cp.async.wait_group 0;" ::: "memory"); }
__device__ __forceinline__ unsigned h2u(__half2 h) { return *(unsigned*)&h; }

// ---------------- SMEM layout (bytes) ----------------
// A: 128 rows x 200 halves (stride 400B)  -> 51200 B   (K=192 used)
// B: 2 buffers x (128 rows x 40 halves = 80B) -> 2 x 10240 B
// bsum: 256 floats
#define A_OFF     0
#define B_OFF     51200
#define BBUF_SZ   10240
#define BSUM_OFF  (B_OFF + 2 * BBUF_SZ)
#define SMEM_BYTES (BSUM_OFF + 1024)

// fp16 weight offsets (in halves): {wih0, whh0, wih1, whh1, wih2, whh2}
__constant__ int c_woff[6] = {0, 32768, 49152, 65536, 81920, 98304};

// ---------------- kernel 0: convert all weights to fp16 ----------------
__global__ void wconv_kernel(const float* __restrict__ wih0, const float* __restrict__ whh0,
                             const float* __restrict__ wih1, const float* __restrict__ whh1,
                             const float* __restrict__ wih2, const float* __restrict__ whh2) {
    int i = blockIdx.x * blockDim.x + threadIdx.x;   // one float2 per thread
    if (i >= 57344) return;
    const float* srcs[6] = {wih0, whh0, wih1, whh1, wih2, whh2};
    int reg, off2;
    if (i < 16384) { reg = 0; off2 = i; }
    else { int t = i - 16384; reg = 1 + t / 8192; off2 = t - (reg - 1) * 8192; }
    float2 v = ((const float2*)srcs[reg])[off2];
    int base2 = (reg == 0) ? 0 : (16384 + (reg - 1) * 8192);
    ((__half2*)g_w16)[base2 + off2] = __floats2half2_rn(v.x, v.y);
}

// ---------------- kernel 1: per-row squared norms ----------------
__global__ void norm2_kernel(const float* __restrict__ feat, int n) {
    int w = (blockIdx.x * blockDim.x + threadIdx.x) >> 5;
    int lane = threadIdx.x & 31;
    if (w >= n) return;
    float2 v = *(const float2*)(feat + (size_t)w * 64 + lane * 2);
    float s = v.x * v.x + v.y * v.y;
    #pragma unroll
    for (int o = 16; o; o >>= 1) s += __shfl_down_sync(0xffffffffu, s, o);
    if (lane == 0) g_norm2[w] = s;
}

// ---------------- kernel 2: argmax over neighbors + row gather ----------------
__global__ void gather_kernel(const float* __restrict__ feat, const int* __restrict__ src, int n) {
    int w = (blockIdx.x * blockDim.x + threadIdx.x) >> 5;
    int lane = threadIdx.x & 31;
    if (w >= n) return;
    int s = src[(size_t)w * 32 + lane];
    float bv = g_norm2[s];
    int bj = lane;
    #pragma unroll
    for (int o = 16; o; o >>= 1) {
        float ov = __shfl_down_sync(0xffffffffu, bv, o);
        int oj = __shfl_down_sync(0xffffffffu, bj, o);
        if (ov > bv || (ov == bv && oj < bj)) { bv = ov; bj = oj; }
    }
    bj = __shfl_sync(0xffffffffu, bj, 0);
    int bs = __shfl_sync(0xffffffffu, s, bj);
    float2 v = *(const float2*)(feat + (size_t)bs * 64 + lane * 2);
    *(float2*)(g_hmsg + (size_t)w * 64 + lane * 2) = v;
}

// ---------------- kernel 3: fused 3-layer LSTM (fp16 m16n8k16 mma, N-split) ----------------
__global__ __launch_bounds__(256) void lstm_kernel(
    const float* __restrict__ feature,
    const float* __restrict__ h0, const float* __restrict__ c0,
    const float* __restrict__ bih0, const float* __restrict__ bhh0,
    const float* __restrict__ bih1, const float* __restrict__ bhh1,
    const float* __restrict__ bih2, const float* __restrict__ bhh2,
    float* __restrict__ out, int n)
{
    extern __shared__ char smem[];
    unsigned* Xw = (unsigned*)(smem + A_OFF);        // A as 32-bit words (2 halves each)
    float* bsum = (float*)(smem + BSUM_OFF);
    const uint32_t sbase = smem_u32(smem);

    const int tid = threadIdx.x;
    const int lane = tid & 31;
    const int warp = tid >> 5;
    const int wm = warp >> 1, wn = warp & 1;
    const int gid = lane >> 2, tig = lane & 3;
    const int m0w = wm * 32;
    const int m0 = blockIdx.x * 128;

    // staging role: thread -> (row, 32B half of 64B row)
    const int rp = tid >> 1;
    const int part = tid & 1;
    const int gP0 = (rp >> 5) * 64 + (rp & 31);      // global W row for pass 0
    const uint32_t bdst_local = (uint32_t)(rp * 80 + part * 32);

    const float* bihA[3] = {bih0, bih1, bih2};
    const float* bhhA[3] = {bhh0, bhh1, bhh2};
    const size_t nd = (size_t)n * 64;
    float* out_hs = out + nd;
    float* out_cs = out + 4 * nd;

    // ---- hoisted prologue: stage (l=0,p=0) chunks 0,1 ----
    {
        const __half* s0 = g_w16 + (size_t)gP0 * 128 + part * 16;
        uint32_t d0 = sbase + B_OFF + bdst_local;
        cp16(d0, s0); cp16(d0 + 16, s0 + 8);
        cp_commit();
        const __half* s1 = s0 + 32;
        uint32_t d1 = sbase + B_OFF + BBUF_SZ + bdst_local;
        cp16(d1, s1); cp16(d1 + 16, s1 + 8);
        cp_commit();
    }

    // ---- stage A for layer 0: [hmsg | feature | h0[0]], K=192, fp16 ----
    #pragma unroll 4
    for (int i = 0; i < 24; i++) {
        int idx = tid + (i << 8);
        int m = idx / 48, k4 = idx - m * 48;
        int node = m0 + m;
        float4 v = make_float4(0.f, 0.f, 0.f, 0.f);
        if (node < n) {
            size_t off = (size_t)node * 64;
            if (k4 < 16)      v = *(const float4*)(g_hmsg + off + k4 * 4);
            else if (k4 < 32) v = *(const float4*)(feature + off + (k4 - 16) * 4);
            else              v = *(const float4*)(h0 + off + (k4 - 32) * 4);
        }
        uint2 t;
        t.x = h2u(__floats2half2_rn(v.x, v.y));
        t.y = h2u(__floats2half2_rn(v.z, v.w));
        *(uint2*)(&Xw[m * 100 + k4 * 2]) = t;
    }

    for (int l = 0; l < 3; l++) {
        bsum[tid] = bihA[l][tid] + bhhA[l][tid];
        const int ncg = (l == 0) ? 6 : 4;

        for (int p = 0; p < 2; p++) {
            const int grow = gP0 + p * 32;

            if (!(l == 0 && p == 0)) {
                #pragma unroll 1
                for (int c = 0; c < 2; c++) {
                    const __half* wp; int rs, ko;
                    if (l == 0) { wp = g_w16 + c_woff[0]; rs = 128; ko = c * 32; }
                    else {
                        int reg = (c < 2) ? (2 * l) : (2 * l + 1);   // FIX: wih_l=2l, whh_l=2l+1
                        wp = g_w16 + c_woff[reg]; rs = 64; ko = (c & 1) * 32;
                    }
                    const __half* src = wp + (size_t)grow * rs + ko + part * 16;
                    uint32_t dst = sbase + B_OFF + (c & 1) * BBUF_SZ + bdst_local;
                    cp16(dst, src); cp16(dst + 16, src + 8);
                    cp_commit();
                }
            }

            float acc[2][8][4];
            #pragma unroll
            for (int mf = 0; mf < 2; mf++)
                #pragma unroll
                for (int f = 0; f < 8; f++)
                    #pragma unroll
                    for (int q = 0; q < 4; q++) acc[mf][f][q] = 0.f;

            #pragma unroll 1
            for (int c = 0; c < ncg; c++) {
                if (c < ncg - 1) cp_wait1(); else cp_wait0();
                __syncthreads();

                const unsigned* Bw = (const unsigned*)(smem + B_OFF + (c & 1) * BBUF_SZ);
                const int kw = c * 16;                 // chunk base in words (32 halves)
                #pragma unroll
                for (int ks = 0; ks < 2; ks++) {
                    const int w0 = kw + ks * 8 + tig;
                    unsigned a[2][4];
                    #pragma unroll
                    for (int mf = 0; mf < 2; mf++) {
                        int r = m0w + mf * 16 + gid;
                        a[mf][0] = Xw[r * 100 + w0];
                        a[mf][1] = Xw[(r + 8) * 100 + w0];
                        a[mf][2] = Xw[r * 100 + w0 + 4];
                        a[mf][3] = Xw[(r + 8) * 100 + w0 + 4];
                    }
                    const int bw0 = ks * 8 + tig;
                    #pragma unroll
                    for (int f = 0; f < 8; f++) {
                        int nc = (f >> 1) * 32 + wn * 16 + (f & 1) * 8 + gid;
                        unsigned b0 = Bw[nc * 20 + bw0];
                        unsigned b1 = Bw[nc * 20 + bw0 + 4];
                        mma16(acc[0][f], a[0], b0, b1);
                        mma16(acc[1][f], a[1], b0, b1);
                    }
                }
                __syncthreads();

                int c2 = c + 2;
                if (c2 < ncg) {
                    const __half* wp; int rs, ko;
                    if (l == 0) {
                        if (c2 < 4) { wp = g_w16 + c_woff[0]; rs = 128; ko = c2 * 32; }
                        else        { wp = g_w16 + c_woff[1]; rs = 64;  ko = (c2 - 4) * 32; }
                    } else {
                        int reg = (c2 < 2) ? (2 * l) : (2 * l + 1);  // FIX: wih_l=2l, whh_l=2l+1
                        wp = g_w16 + c_woff[reg]; rs = 64; ko = (c2 & 1) * 32;
                    }
                    const __half* src = wp + (size_t)grow * rs + ko + part * 16;
                    uint32_t dst = sbase + B_OFF + (c2 & 1) * BBUF_SZ + bdst_local;
                    cp16(dst, src); cp16(dst + 16, src + 8);
                    cp_commit();
                }
            }

            // ---------------- epilogue for this pass ----------------
            {
                const float* cg = c0 + (size_t)l * nd;
                const float* h0n = h0 + (size_t)(l + 1) * nd;
                float* hs_l = out_hs + (size_t)l * nd;
                float* cs_l = out_cs + (size_t)l * nd;

                #pragma unroll
                for (int mf = 0; mf < 2; mf++)
                    #pragma unroll
                    for (int jf = 0; jf < 2; jf++) {
                        const int d0 = p * 32 + wn * 16 + jf * 8 + 2 * tig;
                        #pragma unroll
                        for (int rh = 0; rh < 2; rh++) {
                            const int row = m0w + mf * 16 + gid + rh * 8;
                            const int node = m0 + row;
                            const bool valid = node < n;
                            const size_t noff = (size_t)node * 64;
                            float2 cp2 = make_float2(0.f, 0.f);
                            if (valid) cp2 = *(const float2*)(cg + noff + d0);
                            float hv[2], cv[2];
                            #pragma unroll
                            for (int q = 0; q < 2; q++) {
                                const int pp = rh * 2 + q;
                                const int d = d0 + q;
                                float iv = acc[mf][0 + jf][pp] + bsum[d];
                                float fv = acc[mf][2 + jf][pp] + bsum[64 + d];
                                float gv = acc[mf][4 + jf][pp] + bsum[128 + d];
                                float ov = acc[mf][6 + jf][pp] + bsum[192 + d];
                                float cprev = q ? cp2.y : cp2.x;
                                float cn = fsig(fv) * cprev + fsig(iv) * ftanh(gv);
                                hv[q] = fsig(ov) * ftanh(cn);
                                cv[q] = cn;
                            }
                            if (valid) {
                                *(float2*)(hs_l + noff + d0) = make_float2(hv[0], hv[1]);
                                *(float2*)(cs_l + noff + d0) = make_float2(cv[0], cv[1]);
                                if (l == 2) *(float2*)(out + noff + d0) = make_float2(hv[0], hv[1]);
                            }
                            // A rebuild only after the layer's final pass
                            if (l < 2 && p == 1) {
                                Xw[row * 100 + (d0 >> 1)] = h2u(__floats2half2_rn(hv[0], hv[1]));
                                float2 hh = make_float2(0.f, 0.f);
                                if (valid) hh = *(const float2*)(h0n + noff + d0);
                                Xw[row * 100 + 32 + (d0 >> 1)] = h2u(__floats2half2_rn(hh.x, hh.y));
                                const int dp = d0 - 32;
                                float2 hp = make_float2(0.f, 0.f), h2 = make_float2(0.f, 0.f);
                                if (valid) {
                                    hp = *(const float2*)(hs_l + noff + dp);
                                    h2 = *(const float2*)(h0n + noff + dp);
                                }
                                Xw[row * 100 + (dp >> 1)]      = h2u(__floats2half2_rn(hp.x, hp.y));
                                Xw[row * 100 + 32 + (dp >> 1)] = h2u(__floats2half2_rn(h2.x, h2.y));
                            }
                        }
                    }
                __syncthreads();
            }
        }
    }
}

// ---------------- launch ----------------
extern "C" void kernel_launch(void* const* d_in, const int* in_sizes, int n_in,
                              void* d_out, int out_size) {
    const float* feature = (const float*)d_in[0];
    const int* src       = (const int*)d_in[1];
    const float* h0      = (const float*)d_in[2];
    const float* c0      = (const float*)d_in[3];
    const float* wih0    = (const float*)d_in[4];
    const float* whh0    = (const float*)d_in[5];
    const float* bih0    = (const float*)d_in[6];
    const float* bhh0    = (const float*)d_in[7];
    const float* wih1    = (const float*)d_in[8];
    const float* whh1    = (const float*)d_in[9];
    const float* bih1    = (const float*)d_in[10];
    const float* bhh1    = (const float*)d_in[11];
    const float* wih2    = (const float*)d_in[12];
    const float* whh2    = (const float*)d_in[13];
    const float* bih2    = (const float*)d_in[14];
    const float* bhh2    = (const float*)d_in[15];
    float* out = (float*)d_out;

    int n = in_sizes[0] / 64;

    cudaFuncSetAttribute(lstm_kernel, cudaFuncAttributeMaxDynamicSharedMemorySize, SMEM_BYTES);

    wconv_kernel<<<224, 256>>>(wih0, whh0, wih1, whh1, wih2, whh2);

    int wblocks = (n + 7) / 8;
    norm2_kernel<<<wblocks, 256>>>(feature, n);
    gather_kernel<<<wblocks, 256>>>(feature, src, n);

    int lblocks = (n + 127) / 128;
    lstm_kernel<<<lblocks, 256, SMEM_BYTES>>>(
        feature, h0, c0,
        bih0, bhh0, bih1, bhh1, bih2, bhh2,
        out, n);
}

// round 7
// speedup vs baseline: 3.9635x; 1.0087x over previous
#include <cuda_runtime.h>
#include <cuda_fp16.h>
#include <cstdint>
#include <math.h>

#define NMAX 100000

// ---------------- device scratch ----------------
__device__ float g_norm2[NMAX];
__device__ float g_hmsg[(size_t)NMAX * 64];
// fp16 weights: wih0[256x128] | whh0[256x64] | wih1 | whh1 | wih2 | whh2 (each 256x64)
__device__ __align__(16) __half g_w16[114688];

// ---------------- helpers ----------------
__device__ __forceinline__ void mma16(float* c, const unsigned* a, unsigned b0, unsigned b1) {
    asm volatile(
        "mma.sync.aligned.m16n8k16.row.col.f32.f16.f16.f32 "
        "{%0,%1,%2,%3}, {%4,%5,%6,%7}, {%8,%9}, {%0,%1,%2,%3};\n"
        : "+f"(c[0]), "+f"(c[1]), "+f"(c[2]), "+f"(c[3])
        : "r"(a[0]), "r"(a[1]), "r"(a[2]), "r"(a[3]), "r"(b0), "r"(b1));
}
__device__ __forceinline__ float tanha(float x) {
    float y;
    asm("tanh.approx.f32 %0, %1;" : "=f"(y) : "f"(x));
    return y;
}
__device__ __forceinline__ float fsig(float x) {          // sigmoid via 1-MUFU tanh
    return fmaf(0.5f, tanha(0.5f * x), 0.5f);
}
__device__ __forceinline__ float ftanh(float x) {         // accurate tanh (exp-based)
    float a = fabsf(x);
    float e = __expf(-2.0f * a);
    float t = __fdividef(1.0f - e, 1.0f + e);
    return copysignf(t, x);
}
__device__ __forceinline__ uint32_t smem_u32(const void* p) {
    uint32_t a;
    asm("{ .reg .u64 t; cvta.to.shared.u64 t, %1; cvt.u32.u64 %0, t; }" : "=r"(a) : "l"(p));
    return a;
}
__device__ __forceinline__ void cp16(uint32_t dst, const void* src) {
    asm volatile("cp.async.ca.shared.global [%0], [%1], 16;" :: "r"(dst), "l"(src) : "memory");
}
__device__ __forceinline__ void cp_commit() { asm volatile("cp.async.commit_group;" ::: "memory"); }
__device__ __forceinline__ void cp_wait1()  { asm volatile("cp.async.wait_group 1;" ::: "memory"); }
__device__ __forceinline__ void cp_wait0()  { asm volatile("cp.async.wait_group 0;" ::: "memory"); }
__device__ __forceinline__ unsigned h2u(__half2 h) { return *(unsigned*)&h; }

// ---------------- SMEM layout (bytes) ----------------
// A: 128 rows x 200 halves (stride 400B)  -> 51200 B   (K=192 used)
// B: 2 buffers x (128 rows x 40 halves = 80B) -> 2 x 10240 B
// bsum: 256 floats
#define A_OFF     0
#define B_OFF     51200
#define BBUF_SZ   10240
#define BSUM_OFF  (B_OFF + 2 * BBUF_SZ)
#define SMEM_BYTES (BSUM_OFF + 1024)

// fp16 weight offsets (in halves): {wih0, whh0, wih1, whh1, wih2, whh2}
__constant__ int c_woff[6] = {0, 32768, 49152, 65536, 81920, 98304};

// ---------------- kernel 0: convert all weights to fp16 ----------------
__global__ void wconv_kernel(const float* __restrict__ wih0, const float* __restrict__ whh0,
                             const float* __restrict__ wih1, const float* __restrict__ whh1,
                             const float* __restrict__ wih2, const float* __restrict__ whh2) {
    int i = blockIdx.x * blockDim.x + threadIdx.x;   // one float2 per thread
    if (i >= 57344) return;
    const float* srcs[6] = {wih0, whh0, wih1, whh1, wih2, whh2};
    int reg, off2;
    if (i < 16384) { reg = 0; off2 = i; }
    else { int t = i - 16384; reg = 1 + t / 8192; off2 = t - (reg - 1) * 8192; }
    float2 v = ((const float2*)srcs[reg])[off2];
    int base2 = (reg == 0) ? 0 : (16384 + (reg - 1) * 8192);
    ((__half2*)g_w16)[base2 + off2] = __floats2half2_rn(v.x, v.y);
}

// ---------------- kernel 1: per-row squared norms (16 lanes/row, float4) ----------------
__global__ void norm2_kernel(const float* __restrict__ feat, int n) {
    int half = (blockIdx.x * blockDim.x + threadIdx.x) >> 4;   // one 16-lane group per row
    int sl = threadIdx.x & 15;
    if (half >= n) return;
    float4 v = *(const float4*)(feat + (size_t)half * 64 + sl * 4);
    float s = v.x * v.x + v.y * v.y + v.z * v.z + v.w * v.w;
    #pragma unroll
    for (int o = 8; o; o >>= 1) s += __shfl_down_sync(0xffffffffu, s, o, 16);
    if (sl == 0) g_norm2[half] = s;
}

// ---------------- kernel 2: argmax over neighbors + row gather ----------------
__global__ void gather_kernel(const float* __restrict__ feat, const int* __restrict__ src, int n) {
    int w = (blockIdx.x * blockDim.x + threadIdx.x) >> 5;
    int lane = threadIdx.x & 31;
    if (w >= n) return;
    int s = src[(size_t)w * 32 + lane];
    float bv = g_norm2[s];
    int bj = lane;
    #pragma unroll
    for (int o = 16; o; o >>= 1) {
        float ov = __shfl_down_sync(0xffffffffu, bv, o);
        int oj = __shfl_down_sync(0xffffffffu, bj, o);
        if (ov > bv || (ov == bv && oj < bj)) { bv = ov; bj = oj; }
    }
    bj = __shfl_sync(0xffffffffu, bj, 0);
    int bs = __shfl_sync(0xffffffffu, s, bj);
    float2 v = *(const float2*)(feat + (size_t)bs * 64 + lane * 2);
    *(float2*)(g_hmsg + (size_t)w * 64 + lane * 2) = v;
}

// ---------------- kernel 3: fused 3-layer LSTM (fp16 m16n8k16 mma, N-split) ----------------
__global__ __launch_bounds__(256, 2) void lstm_kernel(
    const float* __restrict__ feature,
    const float* __restrict__ h0, const float* __restrict__ c0,
    const float* __restrict__ bih0, const float* __restrict__ bhh0,
    const float* __restrict__ bih1, const float* __restrict__ bhh1,
    const float* __restrict__ bih2, const float* __restrict__ bhh2,
    float* __restrict__ out, int n)
{
    extern __shared__ char smem[];
    unsigned* Xw = (unsigned*)(smem + A_OFF);        // A as 32-bit words (2 halves each)
    float* bsum = (float*)(smem + BSUM_OFF);
    const uint32_t sbase = smem_u32(smem);

    const int tid = threadIdx.x;
    const int lane = tid & 31;
    const int warp = tid >> 5;
    const int wm = warp >> 1, wn = warp & 1;
    const int gid = lane >> 2, tig = lane & 3;
    const int m0w = wm * 32;
    const int m0 = blockIdx.x * 128;

    // staging role: thread -> (row, 32B half of 64B row)
    const int rp = tid >> 1;
    const int part = tid & 1;
    const int gP0 = (rp >> 5) * 64 + (rp & 31);      // global W row for pass 0
    const uint32_t bdst_local = (uint32_t)(rp * 80 + part * 32);

    const float* bihA[3] = {bih0, bih1, bih2};
    const float* bhhA[3] = {bhh0, bhh1, bhh2};
    const size_t nd = (size_t)n * 64;
    float* out_hs = out + nd;
    float* out_cs = out + 4 * nd;

    // ---- hoisted prologue: stage (l=0,p=0) chunks 0,1 ----
    {
        const __half* s0 = g_w16 + (size_t)gP0 * 128 + part * 16;
        uint32_t d0 = sbase + B_OFF + bdst_local;
        cp16(d0, s0); cp16(d0 + 16, s0 + 8);
        cp_commit();
        const __half* s1 = s0 + 32;
        uint32_t d1 = sbase + B_OFF + BBUF_SZ + bdst_local;
        cp16(d1, s1); cp16(d1 + 16, s1 + 8);
        cp_commit();
    }

    // ---- stage A for layer 0: [hmsg | feature | h0[0]], K=192, fp16 ----
    #pragma unroll 4
    for (int i = 0; i < 24; i++) {
        int idx = tid + (i << 8);
        int m = idx / 48, k4 = idx - m * 48;
        int node = m0 + m;
        float4 v = make_float4(0.f, 0.f, 0.f, 0.f);
        if (node < n) {
            size_t off = (size_t)node * 64;
            if (k4 < 16)      v = *(const float4*)(g_hmsg + off + k4 * 4);
            else if (k4 < 32) v = *(const float4*)(feature + off + (k4 - 16) * 4);
            else              v = *(const float4*)(h0 + off + (k4 - 32) * 4);
        }
        uint2 t;
        t.x = h2u(__floats2half2_rn(v.x, v.y));
        t.y = h2u(__floats2half2_rn(v.z, v.w));
        *(uint2*)(&Xw[m * 100 + k4 * 2]) = t;
    }

    for (int l = 0; l < 3; l++) {
        bsum[tid] = bihA[l][tid] + bhhA[l][tid];
        const int ncg = (l == 0) ? 6 : 4;

        for (int p = 0; p < 2; p++) {
            const int grow = gP0 + p * 32;

            if (!(l == 0 && p == 0)) {
                #pragma unroll 1
                for (int c = 0; c < 2; c++) {
                    const __half* wp; int rs, ko;
                    if (l == 0) { wp = g_w16 + c_woff[0]; rs = 128; ko = c * 32; }
                    else {
                        int reg = (c < 2) ? (2 * l) : (2 * l + 1);
                        wp = g_w16 + c_woff[reg]; rs = 64; ko = (c & 1) * 32;
                    }
                    const __half* src = wp + (size_t)grow * rs + ko + part * 16;
                    uint32_t dst = sbase + B_OFF + (c & 1) * BBUF_SZ + bdst_local;
                    cp16(dst, src); cp16(dst + 16, src + 8);
                    cp_commit();
                }
            }

            float acc[2][8][4];
            #pragma unroll
            for (int mf = 0; mf < 2; mf++)
                #pragma unroll
                for (int f = 0; f < 8; f++)
                    #pragma unroll
                    for (int q = 0; q < 4; q++) acc[mf][f][q] = 0.f;

            #pragma unroll 1
            for (int c = 0; c < ncg; c++) {
                if (c < ncg - 1) cp_wait1(); else cp_wait0();
                __syncthreads();

                const unsigned* Bw = (const unsigned*)(smem + B_OFF + (c & 1) * BBUF_SZ);
                const int kw = c * 16;                 // chunk base in words (32 halves)
                #pragma unroll
                for (int ks = 0; ks < 2; ks++) {
                    const int w0 = kw + ks * 8 + tig;
                    unsigned a[2][4];
                    #pragma unroll
                    for (int mf = 0; mf < 2; mf++) {
                        int r = m0w + mf * 16 + gid;
                        a[mf][0] = Xw[r * 100 + w0];
                        a[mf][1] = Xw[(r + 8) * 100 + w0];
                        a[mf][2] = Xw[r * 100 + w0 + 4];
                        a[mf][3] = Xw[(r + 8) * 100 + w0 + 4];
                    }
                    const int bw0 = ks * 8 + tig;
                    #pragma unroll
                    for (int f = 0; f < 8; f++) {
                        int nc = (f >> 1) * 32 + wn * 16 + (f & 1) * 8 + gid;
                        unsigned b0 = Bw[nc * 20 + bw0];
                        unsigned b1 = Bw[nc * 20 + bw0 + 4];
                        mma16(acc[0][f], a[0], b0, b1);
                        mma16(acc[1][f], a[1], b0, b1);
                    }
                }
                __syncthreads();

                int c2 = c + 2;
                if (c2 < ncg) {
                    const __half* wp; int rs, ko;
                    if (l == 0) {
                        if (c2 < 4) { wp = g_w16 + c_woff[0]; rs = 128; ko = c2 * 32; }
                        else        { wp = g_w16 + c_woff[1]; rs = 64;  ko = (c2 - 4) * 32; }
                    } else {
                        int reg = (c2 < 2) ? (2 * l) : (2 * l + 1);
                        wp = g_w16 + c_woff[reg]; rs = 64; ko = (c2 & 1) * 32;
                    }
                    const __half* src = wp + (size_t)grow * rs + ko + part * 16;
                    uint32_t dst = sbase + B_OFF + (c2 & 1) * BBUF_SZ + bdst_local;
                    cp16(dst, src); cp16(dst + 16, src + 8);
                    cp_commit();
                }
            }

            // ---------------- epilogue for this pass ----------------
            {
                const float* cg = c0 + (size_t)l * nd;
                const float* h0n = h0 + (size_t)(l + 1) * nd;
                float* hs_l = out_hs + (size_t)l * nd;
                float* cs_l = out_cs + (size_t)l * nd;

                #pragma unroll
                for (int mf = 0; mf < 2; mf++)
                    #pragma unroll
                    for (int jf = 0; jf < 2; jf++) {
                        const int d0 = p * 32 + wn * 16 + jf * 8 + 2 * tig;
                        #pragma unroll
                        for (int rh = 0; rh < 2; rh++) {
                            const int row = m0w + mf * 16 + gid + rh * 8;
                            const int node = m0 + row;
                            const bool valid = node < n;
                            const size_t noff = (size_t)node * 64;
                            float2 cp2 = make_float2(0.f, 0.f);
                            if (valid) cp2 = *(const float2*)(cg + noff + d0);
                            float hv[2], cv[2];
                            #pragma unroll
                            for (int q = 0; q < 2; q++) {
                                const int pp = rh * 2 + q;
                                const int d = d0 + q;
                                float iv = acc[mf][0 + jf][pp] + bsum[d];
                                float fv = acc[mf][2 + jf][pp] + bsum[64 + d];
                                float gv = acc[mf][4 + jf][pp] + bsum[128 + d];
                                float ov = acc[mf][6 + jf][pp] + bsum[192 + d];
                                float cprev = q ? cp2.y : cp2.x;
                                float cn = fsig(fv) * cprev + fsig(iv) * ftanh(gv);
                                hv[q] = fsig(ov) * ftanh(cn);
                                cv[q] = cn;
                            }
                            if (valid) {
                                *(float2*)(hs_l + noff + d0) = make_float2(hv[0], hv[1]);
                                *(float2*)(cs_l + noff + d0) = make_float2(cv[0], cv[1]);
                                if (l == 2) *(float2*)(out + noff + d0) = make_float2(hv[0], hv[1]);
                            }
                            // A rebuild only after the layer's final pass
                            if (l < 2 && p == 1) {
                                Xw[row * 100 + (d0 >> 1)] = h2u(__floats2half2_rn(hv[0], hv[1]));
                                float2 hh = make_float2(0.f, 0.f);
                                if (valid) hh = *(const float2*)(h0n + noff + d0);
                                Xw[row * 100 + 32 + (d0 >> 1)] = h2u(__floats2half2_rn(hh.x, hh.y));
                                const int dp = d0 - 32;
                                float2 hp = make_float2(0.f, 0.f), h2 = make_float2(0.f, 0.f);
                                if (valid) {
                                    hp = *(const float2*)(hs_l + noff + dp);
                                    h2 = *(const float2*)(h0n + noff + dp);
                                }
                                Xw[row * 100 + (dp >> 1)]      = h2u(__floats2half2_rn(hp.x, hp.y));
                                Xw[row * 100 + 32 + (dp >> 1)] = h2u(__floats2half2_rn(h2.x, h2.y));
                            }
                        }
                    }
                __syncthreads();
            }
        }
    }
}

// ---------------- launch ----------------
extern "C" void kernel_launch(void* const* d_in, const int* in_sizes, int n_in,
                              void* d_out, int out_size) {
    const float* feature = (const float*)d_in[0];
    const int* src       = (const int*)d_in[1];
    const float* h0      = (const float*)d_in[2];
    const float* c0      = (const float*)d_in[3];
    const float* wih0    = (const float*)d_in[4];
    const float* whh0    = (const float*)d_in[5];
    const float* bih0    = (const float*)d_in[6];
    const float* bhh0    = (const float*)d_in[7];
    const float* wih1    = (const float*)d_in[8];
    const float* whh1    = (const float*)d_in[9];
    const float* bih1    = (const float*)d_in[10];
    const float* bhh1    = (const float*)d_in[11];
    const float* wih2    = (const float*)d_in[12];
    const float* whh2    = (const float*)d_in[13];
    const float* bih2    = (const float*)d_in[14];
    const float* bhh2    = (const float*)d_in[15];
    float* out = (float*)d_out;

    int n = in_sizes[0] / 64;

    cudaFuncSetAttribute(lstm_kernel, cudaFuncAttributeMaxDynamicSharedMemorySize, SMEM_BYTES);

    wconv_kernel<<<224, 256>>>(wih0, whh0, wih1, whh1, wih2, whh2);

    int nblocks = (n * 16 + 255) / 256;   // 16 lanes per row
    norm2_kernel<<<nblocks, 256>>>(feature, n);
    int wblocks = (n + 7) / 8;
    gather_kernel<<<wblocks, 256>>>(feature, src, n);

    int lblocks = (n + 127) / 128;
    lstm_kernel<<<lblocks, 256, SMEM_BYTES>>>(
        feature, h0, c0,
        bih0, bhh0, bih1, bhh1, bih2, bhh2,
        out, n);
}